// round 6
// baseline (speedup 1.0000x reference)
#include <cuda_runtime.h>
#include <cstdint>

// Problem constants
#define BB   4
#define SS   2048
#define DD   768
#define NH   4
#define KK   4
#define DH   192          // DD / NH
#define MM   (BB*SS)      // 8192 GEMM rows

// Scan decomposition
#define CSIZE 4           // CTAs per (head,batch) cluster
#define ESL   (DH/CSIZE)  // 48: e-slice per CTA
#define NT    (4*ESL)     // 192 threads: 4 gates x 48 outputs

// Scratch (device globals; no allocation allowed)
__device__ float g_xconv[BB*SS*DD];      // 25 MB
__device__ float g_pre[4*BB*SS*DD];      // 100 MB: gate pre-activations [g][b][s][d]
__device__ float g_y[BB*SS*DD];          // 25 MB: hidden states pre-LN

__device__ __forceinline__ uint32_t smem_u32(const void* p) {
    return (uint32_t)__cvta_generic_to_shared(p);
}

// ---------------------------------------------------------------------------
// Stage 1: causal depthwise conv1d + bias + swish
// ---------------------------------------------------------------------------
__global__ void conv_swish_kernel(const float* __restrict__ x,
                                  const float* __restrict__ ck,
                                  const float* __restrict__ cb) {
    int idx = blockIdx.x * blockDim.x + threadIdx.x;
    if (idx >= BB*SS*DD) return;
    int d = idx % DD;
    int s = (idx / DD) % SS;
    float acc = cb[d];
#pragma unroll
    for (int j = 0; j < KK; j++) {
        int ss = s - (KK-1) + j;
        if (ss >= 0) acc = fmaf(x[idx + (j - (KK-1))*DD], ck[j*DD + d], acc);
    }
    g_xconv[idx] = acc / (1.f + expf(-acc));   // swish
}

// ---------------------------------------------------------------------------
// Stage 2: block-diagonal gate projections.
// out[g][m][h*DH+e] = sum_d in[m][h*DH+d] * W_g[h][d][e]
// g in {0:i (x_conv), 1:f (x_conv), 2:z (x), 3:o (x)}
// Classic 64x64 smem-tiled fp32 GEMM, BK=16, 256 threads, 4x4 microtile.
// M=8192, N=192, K=192: all tile-exact, no guards.
// ---------------------------------------------------------------------------
__global__ __launch_bounds__(256)
void proj_gemm_kernel(const float* __restrict__ x,
                      const float* __restrict__ Wi, const float* __restrict__ Wf,
                      const float* __restrict__ Wz, const float* __restrict__ Wo) {
    int g = blockIdx.z >> 2;
    int h = blockIdx.z & 3;
    const float* src = (g < 2) ? g_xconv : x;
    const float* W = (g == 0) ? Wi : (g == 1) ? Wf : (g == 2) ? Wz : Wo;
    W += (size_t)h * DH * DH;

    int m0 = blockIdx.x * 64;
    int n0 = blockIdx.y * 64;
    int hcol = h * DH;

    __shared__ float As[16][64];
    __shared__ float Bs[16][64];

    int tid = threadIdx.x;
    int ty = tid >> 4, tx = tid & 15;
    float acc[4][4] = {};

    const float* Ab = src + (size_t)m0 * DD + hcol;

    for (int k0 = 0; k0 < DH; k0 += 16) {
        {   // A tile: 64 rows x 16 k
            int m  = tid >> 2;
            int kq = (tid & 3) * 4;
            float4 a4 = *(const float4*)(Ab + (size_t)m * DD + k0 + kq);
            As[kq+0][m] = a4.x; As[kq+1][m] = a4.y;
            As[kq+2][m] = a4.z; As[kq+3][m] = a4.w;
        }
        {   // B tile: 16 k x 64 e
            int k  = tid >> 4;
            int eq = (tid & 15) * 4;
            *(float4*)&Bs[k][eq] = *(const float4*)(W + (size_t)(k0+k)*DH + n0 + eq);
        }
        __syncthreads();
#pragma unroll
        for (int k = 0; k < 16; k++) {
            float a[4], bv[4];
#pragma unroll
            for (int i = 0; i < 4; i++) a[i]  = As[k][ty*4+i];
#pragma unroll
            for (int j = 0; j < 4; j++) bv[j] = Bs[k][tx*4+j];
#pragma unroll
            for (int i = 0; i < 4; i++)
#pragma unroll
                for (int j = 0; j < 4; j++)
                    acc[i][j] = fmaf(a[i], bv[j], acc[i][j]);
        }
        __syncthreads();
    }

    float* C = g_pre + (size_t)g*MM*DD + (size_t)m0*DD + hcol + n0;
#pragma unroll
    for (int i = 0; i < 4; i++) {
        float4 v = { acc[i][0], acc[i][1], acc[i][2], acc[i][3] };
        *(float4*)(C + (size_t)(ty*4+i)*DD + tx*4) = v;
    }
}

// ---------------------------------------------------------------------------
// Stage 3: sequential sLSTM scan.
// 16 independent (head,batch) problems; cluster of 4 CTAs each.
// Each CTA: 192 threads = (gate g, e-slice of 48). R column lives in 192
// registers per thread. h (192 floats) replicated per CTA in smem, ping-pong
// buffered; h_new slices exchanged via st.shared::cluster + barrier.cluster.
// ---------------------------------------------------------------------------
__global__ void __cluster_dims__(CSIZE, 1, 1) __launch_bounds__(NT, 1)
scan_kernel(const float* __restrict__ Rw, const float* __restrict__ cbias) {
    __shared__ __align__(16) float hbuf[2][DH];
    __shared__ float pre_s[NT];

    int tid = threadIdx.x;
    uint32_t rank;
    asm("mov.u32 %0, %%cluster_ctarank;" : "=r"(rank));
    int prob = blockIdx.x / CSIZE;     // 0..15
    int b = prob >> 2;
    int h = prob & 3;
    int g  = tid / ESL;                // gate 0..3
    int el = tid % ESL;                // 0..47
    int eg = (int)rank * ESL + el;     // e within head, 0..191

    // Load my R column into registers: R[g][h][d][eg], d = 0..191
    float Rreg[DH];
    const float* Rcol = Rw + ((size_t)(g*NH + h) * DH) * DH + eg;
#pragma unroll
    for (int d = 0; d < DH; d++) Rreg[d] = Rcol[(size_t)d * DH];

    float bias = cbias[g*DD + h*DH + eg];

    // Gate pre-activation stream for this thread (prefetched 1 step ahead)
    const float* gp = g_pre + ((size_t)(g*BB + b) * SS) * DD + h*DH + eg;

    // Peer smem addresses for h exchange
    uint32_t hb0 = smem_u32(&hbuf[0][0]);
    uint32_t peer_hb[CSIZE];
#pragma unroll
    for (int p = 0; p < CSIZE; p++)
        asm("mapa.shared::cluster.u32 %0, %1, %2;"
            : "=r"(peer_hb[p]) : "r"(hb0), "r"(p));

    for (int i = tid; i < 2*DH; i += NT) ((float*)hbuf)[i] = 0.f;
    float c = 0.f, n = 0.f, m = 0.f;   // state (only meaningful for tid < ESL)

    asm volatile("barrier.cluster.arrive.aligned;" ::: "memory");
    asm volatile("barrier.cluster.wait.aligned;"   ::: "memory");

    float gin = gp[0];
    float* yout = g_y + ((size_t)b * SS) * DD + h*DH;

    for (int s = 0; s < SS; s++) {
        int cur = s & 1;
        // --- matvec: acc = sum_d R[d][eg] * h[d], 4 indep chains ---
        float a0 = 0.f, a1 = 0.f, a2 = 0.f, a3 = 0.f;
        const float4* h4p = (const float4*)hbuf[cur];
#pragma unroll
        for (int d4 = 0; d4 < DH/4; d4++) {
            float4 h4 = h4p[d4];
            a0 = fmaf(Rreg[4*d4+0], h4.x, a0);
            a1 = fmaf(Rreg[4*d4+1], h4.y, a1);
            a2 = fmaf(Rreg[4*d4+2], h4.z, a2);
            a3 = fmaf(Rreg[4*d4+3], h4.w, a3);
        }
        float pre = (a0 + a1) + (a2 + a3) + gin + bias;
        if (s + 1 < SS) gin = gp[(size_t)(s+1) * DD];   // prefetch next step
        pre_s[tid] = pre;
        __syncthreads();

        if (tid < ESL) {   // these threads own e = eg (their g == 0)
            float it = pre_s[tid];
            float ft = pre_s[ESL   + tid];
            float zt = pre_s[2*ESL + tid];
            float ot = pre_s[3*ESL + tid];
            float mn = fmaxf(ft + m, it);
            float ia = expf(it - mn);
            float fa = expf(ft + m - mn);
            c = fa*c + ia*tanhf(zt);
            n = fa*n + ia;
            m = mn;
            float hv = c / ((1.f + expf(-ot)) * n);   // sigmoid(o)*c/n
            yout[(size_t)s * DD + eg] = hv;
            // broadcast my h slice to all 4 CTAs' next buffer
            uint32_t off = (uint32_t)((((cur ^ 1) * DH) + eg) * 4);
#pragma unroll
            for (int p = 0; p < CSIZE; p++)
                asm volatile("st.shared::cluster.f32 [%0], %1;"
                             :: "r"(peer_hb[p] + off), "f"(hv) : "memory");
        }
        asm volatile("barrier.cluster.arrive.aligned;" ::: "memory");
        asm volatile("barrier.cluster.wait.aligned;"   ::: "memory");
    }
}

// ---------------------------------------------------------------------------
// Stage 4: per-(b,s,head) layernorm over DH=192, scaled by gn_scale.
// One warp per group, 6 values per lane.
// ---------------------------------------------------------------------------
__global__ void ln_kernel(const float* __restrict__ gns, float* __restrict__ out) {
    int gidx = (blockIdx.x * blockDim.x + threadIdx.x) >> 5;
    int lane = threadIdx.x & 31;
    if (gidx >= BB*SS*NH) return;
    int h  = gidx & (NH-1);
    int bs = gidx >> 2;
    const float* yp = g_y + (size_t)bs * DD + h*DH;
    float v[6];
    float sum = 0.f;
#pragma unroll
    for (int i = 0; i < 6; i++) { v[i] = yp[lane + 32*i]; sum += v[i]; }
#pragma unroll
    for (int o = 16; o; o >>= 1) sum += __shfl_xor_sync(0xffffffffu, sum, o);
    float mu = sum * (1.f/DH);
    float sq = 0.f;
#pragma unroll
    for (int i = 0; i < 6; i++) { float t = v[i] - mu; sq += t*t; }
#pragma unroll
    for (int o = 16; o; o >>= 1) sq += __shfl_xor_sync(0xffffffffu, sq, o);
    float rs = rsqrtf(sq * (1.f/DH) + 1e-5f);
    float* op = out + (size_t)bs * DD + h*DH;
#pragma unroll
    for (int i = 0; i < 6; i++) {
        int e = lane + 32*i;
        op[e] = (v[i] - mu) * rs * gns[h*DH + e];
    }
}

// ---------------------------------------------------------------------------
extern "C" void kernel_launch(void* const* d_in, const int* in_sizes, int n_in,
                              void* d_out, int out_size) {
    const float* x     = (const float*)d_in[0];
    const float* ck    = (const float*)d_in[1];
    const float* cb    = (const float*)d_in[2];
    const float* Wi    = (const float*)d_in[3];
    const float* Wf    = (const float*)d_in[4];
    const float* Wz    = (const float*)d_in[5];
    const float* Wo    = (const float*)d_in[6];
    const float* R     = (const float*)d_in[7];
    const float* cbias = (const float*)d_in[8];
    const float* gns   = (const float*)d_in[9];
    float* out = (float*)d_out;

    conv_swish_kernel<<<(BB*SS*DD + 255)/256, 256>>>(x, ck, cb);

    dim3 gg(MM/64, DH/64, 16);   // (128, 3, 16)
    proj_gemm_kernel<<<gg, 256>>>(x, Wi, Wf, Wz, Wo);

    scan_kernel<<<BB*NH*CSIZE, NT>>>(R, cbias);   // 64 CTAs, clusters of 4

    ln_kernel<<<(BB*SS*NH*32 + 255)/256, 256>>>(gns, out);
}